// round 1
// baseline (speedup 1.0000x reference)
#include <cuda_runtime.h>
#include <cuda_bf16.h>

// ---------------- problem constants ----------------
#define W_IMG 135
#define H_IMG 240
#define NPIX (W_IMG * H_IMG)
#define NF 1000
#define NV 600
#define TW 16            // tile width (pixels)
#define TH 8             // tile height (pixels)
#define TX 9             // ceil(135/16)
#define TY 30            // 240/8
#define NT (TX * TY)     // 270 tiles
#define CHUNK 128
#define BLUR_F 9.21024036697585e-04f
#define INV_SIGMA 10000.0f
#define RB 0.0315f       // > sqrt(BLUR) = 0.0303

// ---------------- device scratch (no allocations allowed) ----------------
__device__ float  g_vx[NV];
__device__ float  g_vy[NV];
__device__ float  g_vz[NV];
__device__ float4 g_face[NF * 3];        // {ax,ay,e0x,e0y} {e1x,e1y,e2x,e2y} {r0,r1,r2,-}
__device__ int    g_tileCount[NT];
__device__ int    g_tileList[NT * NF];
__device__ float  g_lossAcc;

// ---------------- kernels ----------------
__global__ void sil_zero_kernel() {
    int i = threadIdx.x;
    if (i < NT) g_tileCount[i] = 0;
    if (i == 0) g_lossAcc = 0.0f;
}

__global__ void sil_project_kernel(const float* __restrict__ verts) {
    int i = blockIdx.x * blockDim.x + threadIdx.x;
    if (i >= NV) return;
    float x = verts[3 * i + 0];
    float y = verts[3 * i + 1];
    float z = verts[3 * i + 2];
    float zc  = fmaxf(z, 1e-6f);
    float inv = 1.0f / zc;
    // px = (1000*(-x)/z + 512)/1024 * W ;  py = (1000*(-y)/z + 512)/1024 * H
    g_vx[i] = (1000.0f * (-x) * inv + 512.0f) * (1.0f / 1024.0f) * (float)W_IMG;
    g_vy[i] = (1000.0f * (-y) * inv + 512.0f) * (1.0f / 1024.0f) * (float)H_IMG;
    g_vz[i] = z;
}

__global__ void sil_bin_kernel(const int* __restrict__ faces) {
    int f = blockIdx.x * blockDim.x + threadIdx.x;
    if (f >= NF) return;
    int i0 = faces[3 * f + 0];
    int i1 = faces[3 * f + 1];
    int i2 = faces[3 * f + 2];
    float ax = g_vx[i0], ay = g_vy[i0];
    float bx = g_vx[i1], by = g_vy[i1];
    float cx = g_vx[i2], cy = g_vy[i2];
    float tz = (g_vz[i0] + g_vz[i1] + g_vz[i2]) * (1.0f / 3.0f);
    if (!(tz > 1e-6f)) return;   // valid=false everywhere -> zero contribution

    float e0x = bx - ax, e0y = by - ay;
    float e1x = cx - bx, e1y = cy - by;
    float e2x = ax - cx, e2y = ay - cy;
    float r0 = 1.0f / (e0x * e0x + e0y * e0y + 1e-12f);
    float r1 = 1.0f / (e1x * e1x + e1y * e1y + 1e-12f);
    float r2 = 1.0f / (e2x * e2x + e2y * e2y + 1e-12f);
    g_face[3 * f + 0] = make_float4(ax, ay, e0x, e0y);
    g_face[3 * f + 1] = make_float4(e1x, e1y, e2x, e2y);
    g_face[3 * f + 2] = make_float4(r0, r1, r2, 0.0f);

    // exact culling: contribution is zero > sqrt(BLUR) away from triangle
    float minx = fminf(ax, fminf(bx, cx)) - RB;
    float maxx = fmaxf(ax, fmaxf(bx, cx)) + RB;
    float miny = fminf(ay, fminf(by, cy)) - RB;
    float maxy = fmaxf(ay, fmaxf(by, cy)) + RB;
    int ixlo = max(0,         (int)floorf(minx - 0.5f));
    int ixhi = min(W_IMG - 1, (int)ceilf (maxx - 0.5f));
    int iylo = max(0,         (int)floorf(miny - 0.5f));
    int iyhi = min(H_IMG - 1, (int)ceilf (maxy - 0.5f));
    if (ixlo > ixhi || iylo > iyhi) return;
    int txlo = ixlo / TW, txhi = ixhi / TW;
    int tylo = iylo / TH, tyhi = iyhi / TH;
    for (int ty = tylo; ty <= tyhi; ty++) {
        for (int tx = txlo; tx <= txhi; tx++) {
            int t = ty * TX + tx;
            int s = atomicAdd(&g_tileCount[t], 1);
            g_tileList[t * NF + s] = f;
        }
    }
}

__global__ void __launch_bounds__(TW * TH)
sil_render_kernel(const float* __restrict__ gt, float* __restrict__ out, int sil_off) {
    __shared__ float4 sF[CHUNK * 3];
    __shared__ float  sRed[4];

    int t   = blockIdx.x;
    int tx  = t % TX, ty = t / TX;
    int tid = threadIdx.x;
    int lx  = tid % TW, ly = tid / TW;
    int ix  = tx * TW + lx;
    int iy  = ty * TH + ly;
    float px = (float)ix + 0.5f;
    float py = (float)iy + 0.5f;
    bool in_range = (ix < W_IMG);

    int n = g_tileCount[t];
    float S = 0.0f;

    for (int c = 0; c < n; c += CHUNK) {
        int m = min(CHUNK, n - c);
        __syncthreads();
        if (tid < m) {
            int f = g_tileList[t * NF + c + tid];
            sF[tid * 3 + 0] = g_face[f * 3 + 0];
            sF[tid * 3 + 1] = g_face[f * 3 + 1];
            sF[tid * 3 + 2] = g_face[f * 3 + 2];
        }
        __syncthreads();
        for (int j = 0; j < m; j++) {
            float4 A = sF[j * 3 + 0];   // ax, ay, e0x, e0y
            float4 B = sF[j * 3 + 1];   // e1x, e1y, e2x, e2y
            float4 R = sF[j * 3 + 2];   // r0, r1, r2

            float apx = px - A.x, apy = py - A.y;
            float bpx = apx - A.z, bpy = apy - A.w;
            float cpx = bpx - B.x, cpy = bpy - B.y;

            float c0 = A.z * apy - A.w * apx;
            float c1 = B.x * bpy - B.y * bpx;
            float c2 = B.z * cpy - B.w * cpx;
            bool pos = (c0 >= 0.0f) & (c1 >= 0.0f) & (c2 >= 0.0f);
            bool neg = (c0 <= 0.0f) & (c1 <= 0.0f) & (c2 <= 0.0f);

            float t0 = fminf(fmaxf((apx * A.z + apy * A.w) * R.x, 0.0f), 1.0f);
            float t1 = fminf(fmaxf((bpx * B.x + bpy * B.y) * R.y, 0.0f), 1.0f);
            float t2 = fminf(fmaxf((cpx * B.z + cpy * B.w) * R.z, 0.0f), 1.0f);
            float dx0 = apx - t0 * A.z, dy0 = apy - t0 * A.w;
            float dx1 = bpx - t1 * B.x, dy1 = bpy - t1 * B.y;
            float dx2 = cpx - t2 * B.z, dy2 = cpy - t2 * B.w;
            float d0 = dx0 * dx0 + dy0 * dy0;
            float d1 = dx1 * dx1 + dy1 * dy1;
            float d2 = dx2 * dx2 + dy2 * dy2;
            float dmin = fminf(d0, fminf(d1, d2));

            bool inside = pos | neg;
            if (inside | (dmin <= BLUR_F)) {
                float x = inside ? dmin * INV_SIGMA : -dmin * INV_SIGMA;
                // log1p(-sigmoid(x)) = -softplus(x)
                float sp = fmaxf(x, 0.0f) + __logf(1.0f + __expf(-fabsf(x)));
                S -= sp;
            }
        }
    }

    float alpha = 1.0f - __expf(S);
    float diff = 0.0f;
    if (in_range) {
        out[sil_off + iy * W_IMG + ix] = alpha;
        diff = fabsf(alpha - gt[iy * W_IMG + ix]);
    }
    // block reduce |alpha - gt|
    #pragma unroll
    for (int o = 16; o > 0; o >>= 1)
        diff += __shfl_down_sync(0xFFFFFFFFu, diff, o);
    if ((tid & 31) == 0) sRed[tid >> 5] = diff;
    __syncthreads();
    if (tid == 0) {
        atomicAdd(&g_lossAcc, sRed[0] + sRed[1] + sRed[2] + sRed[3]);
    }
}

__global__ void sil_finalize_kernel(float* __restrict__ out) {
    out[0] = g_lossAcc * (1.0f / (float)NPIX);
}

// ---------------- launch ----------------
extern "C" void kernel_launch(void* const* d_in, const int* in_sizes, int n_in,
                              void* d_out, int out_size) {
    const float* verts = nullptr;
    const float* gt    = nullptr;
    const int*   faces = nullptr;
    for (int i = 0; i < n_in; i++) {
        if (in_sizes[i] == NV * 3)  verts = (const float*)d_in[i];
        else if (in_sizes[i] == NPIX) gt  = (const float*)d_in[i];
        else if (in_sizes[i] == NF * 3) faces = (const int*)d_in[i];
    }
    float* out = (float*)d_out;
    int sil_off = (out_size > NPIX) ? 1 : 0;   // [loss, sil...] vs [sil...]

    sil_zero_kernel<<<1, NT>>>();
    sil_project_kernel<<<(NV + 255) / 256, 256>>>(verts);
    sil_bin_kernel<<<(NF + 255) / 256, 256>>>(faces);
    sil_render_kernel<<<NT, TW * TH>>>(gt, out, sil_off);
    if (sil_off) sil_finalize_kernel<<<1, 1>>>(out);
}